// round 16
// baseline (speedup 1.0000x reference)
#include <cuda_runtime.h>
#include <cuda_fp16.h>
#include <cstdint>

// ---------------------------------------------------------------------------
// Problem constants
// ---------------------------------------------------------------------------
#define NIMG   64
#define IMGS   224
#define GDIM   14
#define PSZ    16
#define DDIM   768
#define KCLS   768            // per-class K = 16*16*3
#define ROWEL  (IMGS*3)       // 672 elements per image row
#define NPATCH (NIMG * GDIM * GDIM)          // 12544 patch rows
#define CONV_BLOCKS (NPATCH / 8)             // 1568 (8 patches per block)
#define WB_BLOCKS  KCLS                      // 768 weight-build blocks (first)

// GEMM tiling
#define BM      128
#define BN      128
#define BK      64
#define NCHUNKS (KCLS / BK)   // 12

// Scratch: fp16 A in [m][k] patch-major layout (19.3 MB) + fp16 class weights
__device__ __align__(16) __half g_A[NPATCH * KCLS];
__device__ __align__(16) __half g_Bh[9u * KCLS * DDIM];

// ---------------------------------------------------------------------------
// helpers
// ---------------------------------------------------------------------------
__device__ __forceinline__ uint32_t smem_u32(const void* p) {
    uint32_t a;
    asm("{ .reg .u64 t; cvta.to.shared.u64 t, %1; cvt.u32.u64 %0, t; }"
        : "=r"(a) : "l"(p));
    return a;
}

__device__ __forceinline__ void mma_f16(float* c, const uint32_t* a, const uint32_t* b) {
    asm volatile(
        "mma.sync.aligned.m16n8k16.row.col.f32.f16.f16.f32 "
        "{%0,%1,%2,%3}, {%4,%5,%6,%7}, {%8,%9}, {%0,%1,%2,%3};"
        : "+f"(c[0]), "+f"(c[1]), "+f"(c[2]), "+f"(c[3])
        : "r"(a[0]), "r"(a[1]), "r"(a[2]), "r"(a[3]), "r"(b[0]), "r"(b[1]));
}

__device__ __forceinline__ void ldsm_x4(uint32_t* r, uint32_t addr) {
    asm volatile("ldmatrix.sync.aligned.m8n8.x4.shared.b16 {%0,%1,%2,%3}, [%4];"
                 : "=r"(r[0]), "=r"(r[1]), "=r"(r[2]), "=r"(r[3]) : "r"(addr));
}

__device__ __forceinline__ void ldsm_x4t(uint32_t* r, uint32_t addr) {
    asm volatile("ldmatrix.sync.aligned.m8n8.x4.trans.shared.b16 {%0,%1,%2,%3}, [%4];"
                 : "=r"(r[0]), "=r"(r[1]), "=r"(r[2]), "=r"(r[3]) : "r"(addr));
}

#define CP_ASYNC16(dst, src) \
    asm volatile("cp.async.cg.shared.global [%0], [%1], 16;" :: "r"(dst), "l"(src))
#define CP_COMMIT() asm volatile("cp.async.commit_group;" ::: "memory")
#define CP_WAIT1()  asm volatile("cp.async.wait_group 1;" ::: "memory")

__device__ __forceinline__ uint32_t pack_h2(float a, float b) {
    return ((uint32_t)__half_as_ushort(__float2half_rn(b)) << 16)
         | __half_as_ushort(__float2half_rn(a));
}

// ---------------------------------------------------------------------------
// Kernel 0 (fused prep): identical to R13/R15 champion.
// ---------------------------------------------------------------------------
__global__ void prep_kernel(const float* __restrict__ img,
                            const float* __restrict__ W) {
    if (blockIdx.x >= WB_BLOCKS) {
        int blk = blockIdx.x - WB_BLOCKS;
        int w = threadIdx.x >> 5, l = threadIdx.x & 31;
        int p = blk * 8 + w;
        int bimg = p / (GDIM * GDIM);
        int r    = p % (GDIM * GDIM);
        int gh   = r / GDIM;
        int gw   = r % GDIM;
        const float* src = img + (bimg * IMGS + gh * PSZ) * ROWEL + gw * (PSZ * 3);
        __half* dst = g_A + (size_t)p * KCLS;
        #pragma unroll
        for (int j = 0; j < 3; j++) {
            int c   = l + j * 32;          // 0..95
            int row = c / 6;
            int off = (c % 6) * 8;
            const float4* s4 = reinterpret_cast<const float4*>(src + row * ROWEL + off);
            float4 v0 = __ldcs(s4);
            float4 v1 = __ldcs(s4 + 1);
            uint4 hv = make_uint4(pack_h2(v0.x, v0.y), pack_h2(v0.z, v0.w),
                                  pack_h2(v1.x, v1.y), pack_h2(v1.z, v1.w));
            *reinterpret_cast<uint4*>(dst + c * 8) = hv;
        }
        return;
    }

    int k  = blockIdx.x;                 // 0..767
    int pp = k / 3,  cin = k % 3;
    int ph = pp >> 4, pw = pp & 15;

    for (int n = threadIdx.x * 2; n < DDIM; n += blockDim.x * 2) {
        const float* wb = W + (size_t)(pp * 15 + cin) * DDIM + n;
        float2 w0 = __ldcs(reinterpret_cast<const float2*>(wb));
        float2 w1 = __ldcs(reinterpret_cast<const float2*>(wb + 3 * DDIM));
        float2 w2 = __ldcs(reinterpret_cast<const float2*>(wb + 6 * DDIM));
        float2 w3 = __ldcs(reinterpret_cast<const float2*>(wb + 9 * DDIM));
        float2 w4 = __ldcs(reinterpret_cast<const float2*>(wb + 12 * DDIM));

        #pragma unroll
        for (int cls = 0; cls < 9; cls++) {
            int clsH = cls / 3, clsW = cls % 3;
            int th = (clsH == 0 && ph < 8) ? 0 : (clsH == 2 && ph >= 8) ? 2 : 1;
            int tw = (clsW == 0 && pw < 8) ? 0 : (clsW == 2 && pw >= 8) ? 2 : 1;
            float s0 = w0.x, s1 = w0.y;
            if (!(th == 2 || tw == 2)) { s0 += w1.x; s1 += w1.y; }
            if (!(th == 0 || tw == 2)) { s0 += w2.x; s1 += w2.y; }
            if (!(th == 2 || tw == 0)) { s0 += w3.x; s1 += w3.y; }
            if (!(th == 0 || tw == 0)) { s0 += w4.x; s1 += w4.y; }
            size_t o = ((size_t)cls * KCLS + k) * DDIM + n;
            *reinterpret_cast<uint32_t*>(&g_Bh[o]) = pack_h2(s0, s1);
        }
    }
}

// ---------------------------------------------------------------------------
// Kernel 1: class-partitioned fp16 HMMA GEMM (R15 champion structure) with
// one additional change: one-ahead B-fragment prefetch across ks (double-
// buffered bP), so B's ldmatrix latency hides behind the previous ks' MMAs.
// ---------------------------------------------------------------------------
#define A_STRIDE_B 144    // bytes per A smem row (64 fp16 + 8 pad)
#define B_STRIDE_B 272    // bytes per B smem row (128 fp16 + 8 pad)
#define OFF_A   0
#define OFF_B   18432     // 128 * 144
#define STG     35840     // 18432 + 64*272
#define NSTAGE  3
#define SMEM_TOTAL (NSTAGE * STG)   // 107520

__global__ __launch_bounds__(256, 2)
void class_gemm_hmma(const float* __restrict__ bias,
                     float* __restrict__ out) {
    extern __shared__ __align__(16) char smem[];
    const uint32_t sb = smem_u32(smem);

    const int nhv[3]  = {1, 12, 1};
    const int ghbv[3] = {0, 1, 13};

    // map blockIdx.x -> (class, local m-tile)
    int mtl = blockIdx.x;
    int cls = 8;
    #pragma unroll
    for (int c = 0; c < 9; c++) {
        int tiles_c = (NIMG * nhv[c / 3] * nhv[c % 3] + BM - 1) / BM;
        if (mtl < tiles_c) { cls = c; break; }
        mtl -= tiles_c;
    }
    const int clsH = cls / 3, clsW = cls % 3;
    const int nw  = nhv[clsW];
    const int ghb = ghbv[clsH], gwb = ghbv[clsW];
    const int rpi = nhv[clsH] * nw;
    const int Mc  = NIMG * rpi;
    const int m0  = mtl * BM;
    const int n0  = blockIdx.y * BN;

    const int t    = threadIdx.x;
    const int wid  = t >> 5, lane = t & 31;
    const int wm   = wid >> 2;        // 0..1 (m)
    const int wn   = wid & 3;         // 0..3 (n)
    const int gi   = lane >> 2;
    const int li   = lane & 3;
    const int l16  = lane & 15;
    const int lhi  = (lane >> 4) & 1;

    // ---- A cp.async mapping: 4 segments per thread (BK=64) ----
    int arow_[4], aseg_[4];
    uint32_t abase_[4], asz_[4];
    #pragma unroll
    for (int i = 0; i < 4; i++) {
        int idx = i * 256 + t;
        int row = idx >> 3;
        arow_[i] = row;
        aseg_[i] = idx & 7;
        int am = m0 + row;
        bool v = am < Mc;
        int mm = v ? am : 0;
        int bimg = mm / rpi;
        int r    = mm % rpi;
        int gh   = ghb + r / nw;
        int gw   = gwb + r % nw;
        int p    = bimg * (GDIM * GDIM) + gh * GDIM + gw;
        abase_[i] = (uint32_t)(p * KCLS);
        asz_[i]   = v ? 16u : 0u;
    }

    const __half* gB = g_Bh + ((size_t)cls * KCLS) * DDIM + n0;

    // ldmatrix base offsets
    const uint32_t a_ld = (uint32_t)((wm * 64 + l16) * A_STRIDE_B + lhi * 16);
    const uint32_t b_ld = (uint32_t)(l16 * B_STRIDE_B + wn * 64 + lhi * 16);

    float acc[4][4][4];
    #pragma unroll
    for (int i = 0; i < 4; i++)
        #pragma unroll
        for (int j = 0; j < 4; j++)
            #pragma unroll
            for (int q = 0; q < 4; q++) acc[i][j][q] = 0.f;

    // bias is a kernel input (not produced by prep) -> safe before the sync
    float2 bb[4];
    #pragma unroll
    for (int nf = 0; nf < 4; nf++)
        bb[nf] = *reinterpret_cast<const float2*>(bias + n0 + wn * 32 + nf * 8 + li * 2);

    // Wait for prep kernel's writes (g_A, g_Bh) to be visible (PDL).
    cudaGridDependencySynchronize();

    // ---------------- async tile loader ----------------
    auto issue_loads = [&](int c, uint32_t dst) {
        const int kt = c * BK;
        // A (linear [m][k]): 4 x 16B per thread, fully coalesced
        #pragma unroll
        for (int i = 0; i < 4; i++) {
            const __half* src = g_A + abase_[i] + kt + aseg_[i] * 8;
            uint32_t doff = (uint32_t)(arow_[i] * A_STRIDE_B + aseg_[i] * 16);
            asm volatile("cp.async.cg.shared.global [%0], [%1], 16, %2;"
                         :: "r"(dst + OFF_A + doff), "l"(src), "r"(asz_[i]));
        }
        // B: 4 x 16B per thread
        #pragma unroll
        for (int i = 0; i < 4; i++) {
            int idx = i * 256 + t;
            int row = idx >> 4;          // 0..63
            int seg = idx & 15;
            const __half* src = gB + (size_t)(kt + row) * DDIM + seg * 8;
            uint32_t doff = (uint32_t)(row * B_STRIDE_B + seg * 16);
            CP_ASYNC16(dst + OFF_B + doff, src);
        }
        CP_COMMIT();
    };

    // ---------------- pipeline (3-stage, 2 groups in flight) ----------------
    uint32_t st0 = sb, st1 = sb + STG, st2 = sb + 2 * STG;
    issue_loads(0, st0);
    issue_loads(1, st1);

    for (int c = 0; c < NCHUNKS; c++) {
        CP_WAIT1();          // chunk c complete (c+1 still in flight)
        __syncthreads();
        if (c + 2 < NCHUNKS) issue_loads(c + 2, st2);

        // B fragments: double-buffered across ks; prefetch ks+1 during ks MMAs
        uint32_t bP[2][2][4];
        {
            uint32_t bo = st0 + OFF_B + b_ld;
            ldsm_x4t(bP[0][0], bo);
            ldsm_x4t(bP[0][1], bo + 32);
        }
        #pragma unroll
        for (int ks = 0; ks < 4; ks++) {
            const int pbB = ks & 1;
            // one-ahead A-fragment prefetch within ks
            uint32_t aF[2][4];
            uint32_t ao0 = st0 + OFF_A + a_ld + (uint32_t)(ks * 32);
            ldsm_x4(aF[0], ao0);
            #pragma unroll
            for (int mf = 0; mf < 4; mf++) {
                if (mf < 3) {
                    uint32_t ao = st0 + OFF_A + a_ld
                                + (uint32_t)((mf + 1) * 16 * A_STRIDE_B + ks * 32);
                    ldsm_x4(aF[(mf + 1) & 1], ao);
                }
                if (mf == 0 && ks < 3) {
                    // prefetch B fragments for ks+1
                    uint32_t bo = st0 + OFF_B + b_ld
                                + (uint32_t)((ks + 1) * 16 * B_STRIDE_B);
                    ldsm_x4t(bP[pbB ^ 1][0], bo);
                    ldsm_x4t(bP[pbB ^ 1][1], bo + 32);
                }
                #pragma unroll
                for (int nf = 0; nf < 4; nf++)
                    mma_f16(acc[mf][nf], aF[mf & 1],
                            &bP[pbB][nf >> 1][(nf & 1) * 2]);
            }
        }

        // rotate stages: (c, c+1, c+2) -> (c+1, c+2, c+3)
        uint32_t tmp = st0; st0 = st1; st1 = st2; st2 = tmp;
    }

    // ---------------- epilogue ----------------
    #pragma unroll
    for (int mf = 0; mf < 4; mf++) {
        #pragma unroll
        for (int half = 0; half < 2; half++) {
            int m = m0 + wm * 64 + mf * 16 + gi + half * 8;
            if (m < Mc) {
                int bimg = m / rpi;
                int r    = m % rpi;
                int gh   = ghb + r / nw;
                int gw   = gwb + r % nw;
                size_t obase = ((size_t)(bimg * (GDIM * GDIM) + gh * GDIM + gw)) * DDIM
                             + n0 + wn * 32 + li * 2;
                #pragma unroll
                for (int nf = 0; nf < 4; nf++) {
                    float2 v;
                    v.x = acc[mf][nf][half * 2 + 0] + bb[nf].x;
                    v.y = acc[mf][nf][half * 2 + 1] + bb[nf].y;
                    *reinterpret_cast<float2*>(out + obase + nf * 8) = v;
                }
            }
        }
    }
}

// ---------------------------------------------------------------------------
extern "C" void kernel_launch(void* const* d_in, const int* in_sizes, int n_in,
                              void* d_out, int out_size) {
    const float* images = (const float*)d_in[0];
    const float* W      = (const float*)d_in[1];
    const float* bias   = (const float*)d_in[2];
    float* out          = (float*)d_out;

    cudaFuncSetAttribute(class_gemm_hmma,
                         cudaFuncAttributeMaxDynamicSharedMemorySize, SMEM_TOTAL);

    // Kernel 0: prep (W-build blocks first, then image repack)
    prep_kernel<<<WB_BLOCKS + CONV_BLOCKS, 256>>>(images, W);

    // Kernel 1: GEMM via PDL (overlaps prep's tail)
    cudaLaunchConfig_t cfg = {};
    cfg.gridDim  = dim3(100, DDIM / BN, 1);
    cfg.blockDim = dim3(256, 1, 1);
    cfg.dynamicSmemBytes = SMEM_TOTAL;
    cfg.stream = 0;
    cudaLaunchAttribute attrs[1];
    attrs[0].id = cudaLaunchAttributeProgrammaticStreamSerialization;
    attrs[0].val.programmaticStreamSerializationAllowed = 1;
    cfg.attrs = attrs;
    cfg.numAttrs = 1;
    cudaLaunchKernelEx(&cfg, class_gemm_hmma, bias, out);
}